// round 16
// baseline (speedup 1.0000x reference)
#include <cuda_runtime.h>
#include <cuda_fp16.h>
#include <cstdint>

// Problem constants
constexpr int B = 4, S = 1024, D = 1024, H = 16, KH = 4, HD = 64;
constexpr int E = 8, HID = 2816;
constexpr int T = B * S;               // 4096 tokens
constexpr int NREP = H / KH;           // 4

// fp16 GEMM tile config: CTA 128x128, BK=64, 3 stages, 8 warps of 64x32, LDSM
constexpr int STG = 3;
constexpr int AH = 72;                 // halfs per smem row (64 used + 8 pad)
constexpr int ABUF = 128 * AH;
constexpr int BBUF = 128 * AH;
constexpr size_t GSMEM = (size_t)STG * (ABUF + BBUF) * sizeof(__half);  // 110592 B

// fp16 attention: rows padded to 72 halfs
constexpr int AP = 72;
constexpr size_t ATTN_SMEM = (size_t)5 * 64 * AP * sizeof(__half);      // 46080 B

// ---------------- scratch (device globals; no allocation allowed) -------------
__device__ __half g_xn16[(size_t)T * D];
__device__ __half g_q16[(size_t)T * H * HD];
__device__ __half g_k16[(size_t)T * KH * HD];
__device__ __half g_v16[(size_t)T * KH * HD];
__device__ __half g_at16[(size_t)T * H * HD];
__device__ float  g_h [(size_t)T * D];
__device__ float  g_hn[(size_t)T * D];        // fp32 for ROUTER (discrete decisions!)
__device__ __half g_hn16[(size_t)T * D];
__device__ __half g_act16[(size_t)E * T * HID];
__device__ __half g_buf16[(size_t)E * T * D];
__device__ int    g_cnt[E];
__device__ int    g_tok[E * T];
__device__ float  g_wt [E * T];
__device__ int    g_slot[2 * T];
// fp16 transposed weights [N][K]
__device__ __half g_wq16[(size_t)(H * HD) * D];
__device__ __half g_wk16[(size_t)(KH * HD) * D];
__device__ __half g_wv16[(size_t)(KH * HD) * D];
__device__ __half g_wo16[(size_t)D * (H * HD)];
__device__ __half g_w1316[(size_t)E * 2 * HID * D];   // interleaved: even=w1, odd=w3
__device__ __half g_w216[(size_t)E * D * HID];

// ---------------- mma / cp.async / ldmatrix helpers ----------------
__device__ __forceinline__ void mma_f16(float d[4], const uint32_t a[4], const uint32_t b[2]) {
    asm volatile(
        "mma.sync.aligned.m16n8k16.row.col.f32.f16.f16.f32 "
        "{%0,%1,%2,%3},{%4,%5,%6,%7},{%8,%9},{%0,%1,%2,%3};\n"
        : "+f"(d[0]), "+f"(d[1]), "+f"(d[2]), "+f"(d[3])
        : "r"(a[0]), "r"(a[1]), "r"(a[2]), "r"(a[3]), "r"(b[0]), "r"(b[1]));
}
__device__ __forceinline__ void ldsm_x4(uint32_t r[4], uint32_t addr) {
    asm volatile("ldmatrix.sync.aligned.m8n8.x4.shared.b16 {%0,%1,%2,%3}, [%4];"
        : "=r"(r[0]), "=r"(r[1]), "=r"(r[2]), "=r"(r[3]) : "r"(addr));
}
__device__ __forceinline__ void ldsm_x4_t(uint32_t r[4], uint32_t addr) {
    asm volatile("ldmatrix.sync.aligned.m8n8.x4.trans.shared.b16 {%0,%1,%2,%3}, [%4];"
        : "=r"(r[0]), "=r"(r[1]), "=r"(r[2]), "=r"(r[3]) : "r"(addr));
}
__device__ __forceinline__ void cp16(void* dst, const void* src, bool ok) {
    uint32_t d = (uint32_t)__cvta_generic_to_shared(dst);
    int sz = ok ? 16 : 0;
    asm volatile("cp.async.ca.shared.global [%0], [%1], 16, %2;\n"
                 :: "r"(d), "l"(src), "r"(sz));
}
__device__ __forceinline__ void cp_commit() { asm volatile("cp.async.commit_group;\n"); }
template<int N> __device__ __forceinline__ void cp_wait() {
    asm volatile("cp.async.wait_group %0;\n" :: "n"(N));
}

// ------- transpose+convert: [K][N] fp32 -> [N*rs + off][K] fp16, 64x64 tiles --
__global__ __launch_bounds__(256) void transpose_f16_kernel(
        const float* __restrict__ in, __half* __restrict__ out,
        int K, int N, long long inZ, long long outZ, int rs, int off) {
    __shared__ float tile[64][65];
    int z = blockIdx.z;
    const float* inz = in + (size_t)z * inZ;
    __half* outz = out + (size_t)z * outZ;
    int n0 = blockIdx.x * 64, k0 = blockIdx.y * 64;
    int tx = threadIdx.x & 15, ty = threadIdx.x >> 4;
    #pragma unroll
    for (int j = 0; j < 4; j++) {
        int kk = ty + j * 16;
        float4 v = *(const float4*)&inz[(size_t)(k0 + kk) * N + n0 + tx * 4];
        tile[kk][tx * 4 + 0] = v.x; tile[kk][tx * 4 + 1] = v.y;
        tile[kk][tx * 4 + 2] = v.z; tile[kk][tx * 4 + 3] = v.w;
    }
    __syncthreads();
    int sx = threadIdx.x & 7, sy = threadIdx.x >> 3;
    #pragma unroll
    for (int j = 0; j < 2; j++) {
        int nn = sy + j * 32;
        __half tmp[8];
        #pragma unroll
        for (int t = 0; t < 8; t++) tmp[t] = __float2half(tile[sx * 8 + t][nn]);
        *(uint4*)&outz[((size_t)(n0 + nn) * rs + off) * K + k0 + sx * 8] = *(uint4*)tmp;
    }
}

// ---------------- RMSNorm (fp32 and/or fp16 outputs) ----------------
__global__ __launch_bounds__(256) void rmsnorm_kernel(const float* __restrict__ x,
        const float* __restrict__ w, float* __restrict__ out, __half* __restrict__ out16) {
    int row = blockIdx.x;
    const float* xr = x + (size_t)row * D;
    float s = 0.f;
    for (int i = threadIdx.x; i < D; i += 256) { float v = xr[i]; s += v * v; }
    __shared__ float red[256];
    red[threadIdx.x] = s;
    __syncthreads();
    for (int o = 128; o > 0; o >>= 1) {
        if (threadIdx.x < o) red[threadIdx.x] += red[threadIdx.x + o];
        __syncthreads();
    }
    float inv = rsqrtf(red[0] / (float)D + 1e-5f);
    for (int i = threadIdx.x; i < D; i += 256) {
        float v = xr[i] * inv * w[i];
        if (out)   out[(size_t)row * D + i] = v;
        if (out16) out16[(size_t)row * D + i] = __float2half(v);
    }
}

// ============ fp16 GEMM: CTA 128x128, warp 64x32, BK=64, LDSM fragments =======
// A fp16 [m][K]; B fp16 [N][K]. modes: 0 plain, 1 +add(fp32)->fp32,
// 5 fused glu: out half at col/2 = silu(v_even)*v_odd (B rows interleaved w1/w3).
__global__ __launch_bounds__(256, 2) void gemm_f16(
        const __half* __restrict__ A, const __half* __restrict__ Bw,
        float* __restrict__ C, __half* __restrict__ C16,
        const float* __restrict__ add,
        const int* __restrict__ gtok, const int* __restrict__ gcnt,
        int M, int N, int K, int mode,
        long long strideAz, long long strideBz, long long strideCz) {
    int z = blockIdx.z;
    const __half* Az = A + (size_t)z * strideAz;
    const __half* Bz = Bw + (size_t)z * strideBz;
    float* Cz = C ? C + (size_t)z * strideCz : nullptr;
    __half* C16z = C16 ? C16 + (size_t)z * strideCz : nullptr;

    int c = gcnt ? gcnt[z] : M;
    int bm = blockIdx.y * 128;
    if (bm >= c) return;
    int bn = blockIdx.x * 128;

    extern __shared__ __half hsm[];
    __half* As = hsm;
    __half* Bs = hsm + STG * ABUF;
    uint32_t asm_base = (uint32_t)__cvta_generic_to_shared(As);
    uint32_t bsm_base = (uint32_t)__cvta_generic_to_shared(Bs);

    int tid = threadIdx.x;
    int ar = tid >> 1, ac = (tid & 1) * 32;
    const __half* aRow = nullptr;
    if (gtok) {
        if (bm + ar < c) aRow = Az + (size_t)(gtok + z * T)[bm + ar] * K;
    } else {
        if (bm + ar < c) aRow = Az + (size_t)(bm + ar) * K;
    }
    bool aok = aRow != nullptr;
    const __half* bPtr = Bz + (size_t)(bn + ar) * K + ac;

    int warp = tid >> 5, lane = tid & 31;
    int wm = (warp >> 2) * 64, wn = (warp & 3) * 32;
    int lr = lane >> 2, lc = lane & 3;
    int l7 = lane & 7, g = lane >> 3;

    int aoff[4], boff[2];
    #pragma unroll
    for (int mt = 0; mt < 4; mt++)
        aoff[mt] = (wm + mt * 16 + l7 + ((g & 1) << 3)) * AH + ((g >> 1) << 3);
    #pragma unroll
    for (int p = 0; p < 2; p++)
        boff[p] = (wn + (p << 4) + l7 + ((g >> 1) << 3)) * AH + ((g & 1) << 3);

    float acc[4][4][4] = {};

    auto stage = [&](int kb, int buf) {
        int ko = kb * 64;
        const __half* as = aok ? (aRow + ko + ac) : (const __half*)Bz;
        #pragma unroll
        for (int q = 0; q < 4; q++) {
            cp16(&As[buf * ABUF + ar * AH + ac + q * 8], aok ? as + q * 8 : as, aok);
            cp16(&Bs[buf * BBUF + ar * AH + ac + q * 8], bPtr + ko + q * 8, true);
        }
    };

    int nk = K >> 6;
    stage(0, 0); cp_commit();
    stage(1, 1); cp_commit();

    for (int kb = 0; kb < nk; kb++) {
        if (kb + 1 < nk) cp_wait<1>(); else cp_wait<0>();
        __syncthreads();
        int cur = kb % 3;
        uint32_t ab = asm_base + (uint32_t)(cur * ABUF) * 2;
        uint32_t bb = bsm_base + (uint32_t)(cur * BBUF) * 2;
        #pragma unroll
        for (int k8 = 0; k8 < 4; k8++) {
            int kk = k8 * 16;
            uint32_t af[4][4], bf[2][4];
            #pragma unroll
            for (int mt = 0; mt < 4; mt++) ldsm_x4(af[mt], ab + (uint32_t)(aoff[mt] + kk) * 2);
            #pragma unroll
            for (int p = 0; p < 2; p++)    ldsm_x4(bf[p],  bb + (uint32_t)(boff[p] + kk) * 2);
            #pragma unroll
            for (int mt = 0; mt < 4; mt++)
                #pragma unroll
                for (int nt = 0; nt < 4; nt++)
                    mma_f16(acc[mt][nt], af[mt], &bf[nt >> 1][(nt & 1) * 2]);
        }
        if (kb + 2 < nk) { stage(kb + 2, (kb + 2) % 3); cp_commit(); }
    }

    #pragma unroll
    for (int mt = 0; mt < 4; mt++) {
        #pragma unroll
        for (int nt = 0; nt < 4; nt++) {
            int col = bn + wn + nt * 8 + 2 * lc;
            #pragma unroll
            for (int half = 0; half < 2; half++) {
                int r = bm + wm + mt * 16 + lr + half * 8;
                if (r >= c) continue;
                float v0 = acc[mt][nt][half * 2 + 0];
                float v1 = acc[mt][nt][half * 2 + 1];
                if (mode == 5) {
                    float sv = v0 / (1.f + __expf(-v0)) * v1;
                    C16z[(size_t)r * (N >> 1) + (col >> 1)] = __float2half(sv);
                } else {
                    size_t idx = (size_t)r * N + col;
                    if (mode == 1) {
                        v0 += add[idx]; v1 += add[idx + 1];
                        *(float2*)&Cz[idx] = make_float2(v0, v1);
                    } else if (C16z) {
                        *(__half2*)&C16z[idx] = __floats2half2_rn(v0, v1);
                    } else {
                        *(float2*)&Cz[idx] = make_float2(v0, v1);
                    }
                }
            }
        }
    }
}

// ============ fused QKV projection + RoPE -> fp16 q/k/v (q pre-scaled) ========
__global__ __launch_bounds__(256, 2) void qkv_rope_kernel(
        const __half* __restrict__ xn,
        const __half* __restrict__ wq, const __half* __restrict__ wk,
        const __half* __restrict__ wv,
        __half* __restrict__ q, __half* __restrict__ k, __half* __restrict__ v,
        const float* __restrict__ fcos, const float* __restrict__ fsin) {
    int bm = blockIdx.y * 128;
    int bn = blockIdx.x * 128;
    const __half* Bsel; __half* Cout; int Nl, bnn; bool dorope; float osc;
    if (bn < 1024)      { Bsel = wq; Cout = q; Nl = 1024; bnn = bn;        dorope = true;  osc = 0.125f; }
    else if (bn < 1280) { Bsel = wk; Cout = k; Nl = 256;  bnn = bn - 1024; dorope = true;  osc = 1.f; }
    else                { Bsel = wv; Cout = v; Nl = 256;  bnn = bn - 1280; dorope = false; osc = 1.f; }

    extern __shared__ __half hsm[];
    __half* As = hsm;
    __half* Bs = hsm + STG * ABUF;
    uint32_t asm_base = (uint32_t)__cvta_generic_to_shared(As);
    uint32_t bsm_base = (uint32_t)__cvta_generic_to_shared(Bs);

    int tid = threadIdx.x;
    int ar = tid >> 1, ac = (tid & 1) * 32;
    const __half* aRow = xn + (size_t)(bm + ar) * D;
    const __half* bPtr = Bsel + (size_t)(bnn + ar) * D + ac;

    int warp = tid >> 5, lane = tid & 31;
    int wm = (warp >> 2) * 64, wn = (warp & 3) * 32;
    int lr = lane >> 2, lc = lane & 3;
    int l7 = lane & 7, g = lane >> 3;

    int aoff[4], boff[2];
    #pragma unroll
    for (int mt = 0; mt < 4; mt++)
        aoff[mt] = (wm + mt * 16 + l7 + ((g & 1) << 3)) * AH + ((g >> 1) << 3);
    #pragma unroll
    for (int p = 0; p < 2; p++)
        boff[p] = (wn + (p << 4) + l7 + ((g >> 1) << 3)) * AH + ((g & 1) << 3);

    float acc[4][4][4] = {};

    auto stage = [&](int kb, int buf) {
        int ko = kb * 64;
        const __half* as = aRow + ko + ac;
        #pragma unroll
        for (int q2 = 0; q2 < 4; q2++) {
            cp16(&As[buf * ABUF + ar * AH + ac + q2 * 8], as + q2 * 8, true);
            cp16(&Bs[buf * BBUF + ar * AH + ac + q2 * 8], bPtr + ko + q2 * 8, true);
        }
    };

    constexpr int nk = D / 64;             // 16
    stage(0, 0); cp_commit();
    stage(1, 1); cp_commit();

    for (int kb = 0; kb < nk; kb++) {
        if (kb + 1 < nk) cp_wait<1>(); else cp_wait<0>();
        __syncthreads();
        int cur = kb % 3;
        uint32_t ab = asm_base + (uint32_t)(cur * ABUF) * 2;
        uint32_t bb = bsm_base + (uint32_t)(cur * BBUF) * 2;
        #pragma unroll
        for (int k8 = 0; k8 < 4; k8++) {
            int kk = k8 * 16;
            uint32_t af[4][4], bf[2][4];
            #pragma unroll
            for (int mt = 0; mt < 4; mt++) ldsm_x4(af[mt], ab + (uint32_t)(aoff[mt] + kk) * 2);
            #pragma unroll
            for (int p = 0; p < 2; p++)    ldsm_x4(bf[p],  bb + (uint32_t)(boff[p] + kk) * 2);
            #pragma unroll
            for (int mt = 0; mt < 4; mt++)
                #pragma unroll
                for (int nt = 0; nt < 4; nt++)
                    mma_f16(acc[mt][nt], af[mt], &bf[nt >> 1][(nt & 1) * 2]);
        }
        if (kb + 2 < nk) { stage(kb + 2, (kb + 2) % 3); cp_commit(); }
    }

    #pragma unroll
    for (int mt = 0; mt < 4; mt++) {
        #pragma unroll
        for (int nt = 0; nt < 4; nt++) {
            int col = bnn + wn + nt * 8 + 2 * lc;
            int i = (col & 63) >> 1;
            #pragma unroll
            for (int half = 0; half < 2; half++) {
                int r = bm + wm + mt * 16 + lr + half * 8;
                float v0 = acc[mt][nt][half * 2 + 0];
                float v1 = acc[mt][nt][half * 2 + 1];
                if (dorope) {
                    int s = r & (S - 1);
                    float cs = fcos[s * 32 + i], sn = fsin[s * 32 + i];
                    float t0 = v0 * cs - v1 * sn;
                    v1 = v0 * sn + v1 * cs;
                    v0 = t0;
                }
                *(__half2*)&Cout[(size_t)r * Nl + col] = __floats2half2_rn(v0 * osc, v1 * osc);
            }
        }
    }
}

// ============ fp16 tensor-core flash attention (causal, GQA, m16n8k16) ========
__global__ __launch_bounds__(128) void attn_f16_kernel(const __half* __restrict__ q,
        const __half* __restrict__ k, const __half* __restrict__ v,
        __half* __restrict__ o16) {
    extern __shared__ __half hsm[];
    __half* Qs = hsm;
    __half* Ps = hsm;
    __half* Ks = hsm + 64 * AP;
    __half* Vs = Ks + 2 * 64 * AP;
    uint32_t pbase = (uint32_t)__cvta_generic_to_shared(Ps);
    uint32_t kbase = (uint32_t)__cvta_generic_to_shared(Ks);
    uint32_t vbase = (uint32_t)__cvta_generic_to_shared(Vs);

    const int qt = gridDim.x - 1 - blockIdx.x;
    const int h = blockIdx.y, b = blockIdx.z;
    const int kh = h / NREP;
    const int tid = threadIdx.x;
    const int warp = tid >> 5, lane = tid & 31;
    const int lr = lane >> 2, lc = lane & 3;
    const int wm = warp * 16;
    const int l7 = lane & 7, g = lane >> 3;

    const __half* krow = k + ((size_t)(b * S) * KH + kh) * HD;
    const __half* vrow = v + ((size_t)(b * S) * KH + kh) * HD;

    auto stageKV = [&](int kt, int buf) {
        __half* Kd = Ks + buf * 64 * AP;
        __half* Vd = Vs + buf * 64 * AP;
        #pragma unroll
        for (int j = 0; j < 4; j++) {
            int idx = tid + j * 128;
            int row = idx >> 3, ch = (idx & 7) * 8;
            size_t go = (size_t)(kt * 64 + row) * (KH * HD) + ch;
            cp16(&Kd[row * AP + ch], krow + go, true);
            cp16(&Vd[row * AP + ch], vrow + go, true);
        }
    };
    stageKV(0, 0);
    cp_commit();

    #pragma unroll
    for (int j = 0; j < 4; j++) {
        int idx = tid + j * 128;
        int row = idx >> 3, ch = (idx & 7) * 8;
        *(uint4*)&Qs[row * AP + ch] =
            *(const uint4*)&q[(size_t)(b * S + qt * 64 + row) * (H * HD) + h * HD + ch];
    }
    __syncthreads();
    uint32_t qf[4][4];
    #pragma unroll
    for (int ks = 0; ks < 4; ks++) {
        uint32_t addr = pbase + (uint32_t)((wm + l7 + ((g & 1) << 3)) * AP
                                           + ks * 16 + ((g >> 1) << 3)) * 2;
        ldsm_x4(qf[ks], addr);
    }

    float of[8][4] = {};
    float l0 = 0.f, l1 = 0.f;

    for (int kt = 0; kt <= qt; kt++) {
        int cur = kt & 1;
        if (kt < qt) { stageKV(kt + 1, cur ^ 1); cp_commit(); cp_wait<1>(); }
        else         { cp_wait<0>(); }
        __syncthreads();
        uint32_t kb = kbase + (uint32_t)(cur * 64 * AP) * 2;
        uint32_t vb = vbase + (uint32_t)(cur * 64 * AP) * 2;

        float sacc[8][4] = {};
        #pragma unroll
        for (int ks = 0; ks < 4; ks++) {
            #pragma unroll
            for (int np = 0; np < 4; np++) {
                uint32_t bf[4];
                uint32_t addr = kb + (uint32_t)((np * 16 + l7 + ((g >> 1) << 3)) * AP
                                                + ks * 16 + ((g & 1) << 3)) * 2;
                ldsm_x4(bf, addr);
                mma_f16(sacc[np * 2 + 0], qf[ks], &bf[0]);
                mma_f16(sacc[np * 2 + 1], qf[ks], &bf[2]);
            }
        }
        bool diag = (kt == qt);
        float ls0 = 0.f, ls1 = 0.f;
        #pragma unroll
        for (int nt = 0; nt < 8; nt++) {
            int c0 = nt * 8 + 2 * lc;
            int r0 = wm + lr, r1 = r0 + 8;
            float p00 = (diag && (c0     > r0)) ? 0.f : __expf(sacc[nt][0]);
            float p01 = (diag && (c0 + 1 > r0)) ? 0.f : __expf(sacc[nt][1]);
            float p10 = (diag && (c0     > r1)) ? 0.f : __expf(sacc[nt][2]);
            float p11 = (diag && (c0 + 1 > r1)) ? 0.f : __expf(sacc[nt][3]);
            ls0 += p00 + p01; ls1 += p10 + p11;
            *(__half2*)&Ps[r0 * AP + c0] = __floats2half2_rn(p00, p01);
            *(__half2*)&Ps[r1 * AP + c0] = __floats2half2_rn(p10, p11);
        }
        ls0 += __shfl_xor_sync(0xffffffffu, ls0, 1);
        ls0 += __shfl_xor_sync(0xffffffffu, ls0, 2);
        ls1 += __shfl_xor_sync(0xffffffffu, ls1, 1);
        ls1 += __shfl_xor_sync(0xffffffffu, ls1, 2);
        l0 += ls0; l1 += ls1;
        __syncwarp();

        #pragma unroll
        for (int ks = 0; ks < 4; ks++) {
            uint32_t paf[4];
            uint32_t addr = pbase + (uint32_t)((wm + l7 + ((g & 1) << 3)) * AP
                                               + ks * 16 + ((g >> 1) << 3)) * 2;
            ldsm_x4(paf, addr);
            #pragma unroll
            for (int np = 0; np < 4; np++) {
                uint32_t bf[4];
                uint32_t va = vb + (uint32_t)((ks * 16 + l7 + ((g & 1) << 3)) * AP
                                              + np * 16 + ((g >> 1) << 3)) * 2;
                ldsm_x4_t(bf, va);
                mma_f16(of[np * 2 + 0], paf, &bf[0]);
                mma_f16(of[np * 2 + 1], paf, &bf[2]);
            }
        }
        __syncthreads();
    }

    float i0 = 1.f / l0, i1 = 1.f / l1;
    size_t o0 = (size_t)(b * S + qt * 64 + wm + lr) * (H * HD) + h * HD;
    #pragma unroll
    for (int nt = 0; nt < 8; nt++) {
        int c0 = nt * 8 + 2 * lc;
        *(__half2*)&o16[o0 + c0] = __floats2half2_rn(of[nt][0] * i0, of[nt][1] * i0);
        *(__half2*)&o16[o0 + (size_t)8 * (H * HD) + c0] =
            __floats2half2_rn(of[nt][2] * i1, of[nt][3] * i1);
    }
}

// ---------------- router: top-2 of softmax(hn @ gate_w), fp32 (discrete!) -----
__global__ __launch_bounds__(256) void router_kernel(const float* __restrict__ hn,
        const float* __restrict__ gw, int* __restrict__ cnt,
        int* __restrict__ tok, float* __restrict__ wt, int* __restrict__ slot) {
    int t = blockIdx.x;
    int warp = threadIdx.x >> 5, lane = threadIdx.x & 31;
    const float* hr = hn + (size_t)t * D;
    float s = 0.f;
    for (int i = lane; i < D; i += 32) s += hr[i] * gw[i * E + warp];
    #pragma unroll
    for (int o = 16; o > 0; o >>= 1) s += __shfl_xor_sync(0xffffffffu, s, o);
    __shared__ float lg[E];
    if (lane == 0) lg[warp] = s;
    __syncthreads();
    if (threadIdx.x == 0) {
        int i0 = 0;
        for (int i = 1; i < E; i++) if (lg[i] > lg[i0]) i0 = i;
        int i1 = (i0 == 0) ? 1 : 0;
        for (int i = 0; i < E; i++) { if (i == i0) continue; if (lg[i] > lg[i1]) i1 = i; }
        float e1 = expf(lg[i1] - lg[i0]);
        float w0 = 1.f / (1.f + e1);
        float w1 = e1 * w0;
        int p0 = atomicAdd(&cnt[i0], 1);
        tok[i0 * T + p0] = t; wt[i0 * T + p0] = w0;
        int p1 = atomicAdd(&cnt[i1], 1);
        tok[i1 * T + p1] = t; wt[i1 * T + p1] = w1;
        slot[t * 2]     = i0 * T + p0;
        slot[t * 2 + 1] = i1 * T + p1;
    }
}

__global__ void zero_cnt_kernel(int* cnt) { if (threadIdx.x < E) cnt[threadIdx.x] = 0; }

// ---------------- final combine: out = h + w0*buf16[s0] + w1*buf16[s1] --------
__global__ __launch_bounds__(256) void moe_combine_kernel(const float* __restrict__ h,
        const __half* __restrict__ buf, const int* __restrict__ slot,
        const float* __restrict__ wt, float* __restrict__ out) {
    int t = blockIdx.x;
    int s0 = slot[t * 2], s1 = slot[t * 2 + 1];
    float w0 = wt[s0], w1 = wt[s1];
    const float4* h4 = (const float4*)(h + (size_t)t * D);
    const __half2* b0 = (const __half2*)(buf + (size_t)s0 * D);
    const __half2* b1 = (const __half2*)(buf + (size_t)s1 * D);
    float4* o4 = (float4*)(out + (size_t)t * D);
    int i = threadIdx.x;
    float4 hv = h4[i];
    float2 a0 = __half22float2(b0[2 * i]),     a1 = __half22float2(b0[2 * i + 1]);
    float2 c0 = __half22float2(b1[2 * i]),     c1 = __half22float2(b1[2 * i + 1]);
    o4[i] = make_float4(hv.x + w0 * a0.x + w1 * c0.x,
                        hv.y + w0 * a0.y + w1 * c0.y,
                        hv.z + w0 * a1.x + w1 * c1.x,
                        hv.w + w0 * a1.y + w1 * c1.y);
}

// ------------------------------- launch -------------------------------------
extern "C" void kernel_launch(void* const* d_in, const int* in_sizes, int n_in,
                              void* d_out, int out_size) {
    const float* x    = (const float*)d_in[0];
    const float* fcos = (const float*)d_in[3];
    const float* fsin = (const float*)d_in[4];
    const float* anw  = (const float*)d_in[5];
    const float* fnw  = (const float*)d_in[6];
    const float* wq   = (const float*)d_in[7];
    const float* wk   = (const float*)d_in[8];
    const float* wv   = (const float*)d_in[9];
    const float* wo   = (const float*)d_in[10];
    const float* gw   = (const float*)d_in[11];
    const float* w1   = (const float*)d_in[12];
    const float* w2   = (const float*)d_in[13];
    const float* w3   = (const float*)d_in[14];
    float* out = (float*)d_out;

    __half *xn16, *q16, *k16, *v16, *at16, *hn16, *act16, *buf16;
    __half *wq16, *wk16, *wv16, *wo16, *w1316, *w216;
    float *h, *hn, *wt;
    int *cnt, *tok, *slot;
    cudaGetSymbolAddress((void**)&xn16, g_xn16);
    cudaGetSymbolAddress((void**)&q16,  g_q16);
    cudaGetSymbolAddress((void**)&k16,  g_k16);
    cudaGetSymbolAddress((void**)&v16,  g_v16);
    cudaGetSymbolAddress((void**)&at16, g_at16);
    cudaGetSymbolAddress((void**)&h,    g_h);
    cudaGetSymbolAddress((void**)&hn,   g_hn);
    cudaGetSymbolAddress((void**)&hn16, g_hn16);
    cudaGetSymbolAddress((void**)&act16, g_act16);
    cudaGetSymbolAddress((void**)&buf16, g_buf16);
    cudaGetSymbolAddress((void**)&cnt,  g_cnt);
    cudaGetSymbolAddress((void**)&tok,  g_tok);
    cudaGetSymbolAddress((void**)&wt,   g_wt);
    cudaGetSymbolAddress((void**)&slot, g_slot);
    cudaGetSymbolAddress((void**)&wq16, g_wq16);
    cudaGetSymbolAddress((void**)&wk16, g_wk16);
    cudaGetSymbolAddress((void**)&wv16, g_wv16);
    cudaGetSymbolAddress((void**)&wo16, g_wo16);
    cudaGetSymbolAddress((void**)&w1316, g_w1316);
    cudaGetSymbolAddress((void**)&w216, g_w216);

    cudaFuncSetAttribute(attn_f16_kernel, cudaFuncAttributeMaxDynamicSharedMemorySize, (int)ATTN_SMEM);
    cudaFuncSetAttribute(gemm_f16, cudaFuncAttributeMaxDynamicSharedMemorySize, (int)GSMEM);
    cudaFuncSetAttribute(qkv_rope_kernel, cudaFuncAttributeMaxDynamicSharedMemorySize, (int)GSMEM);

    // 0) weight transpose+convert to fp16 [N][K]; w1/w3 interleaved (even/odd rows)
    transpose_f16_kernel<<<dim3(16, 16, 1), 256>>>(wq, wq16, D, H * HD, 0, 0, 1, 0);
    transpose_f16_kernel<<<dim3(4,  16, 1), 256>>>(wk, wk16, D, KH * HD, 0, 0, 1, 0);
    transpose_f16_kernel<<<dim3(4,  16, 1), 256>>>(wv, wv16, D, KH * HD, 0, 0, 1, 0);
    transpose_f16_kernel<<<dim3(16, 16, 1), 256>>>(wo, wo16, H * HD, D, 0, 0, 1, 0);
    transpose_f16_kernel<<<dim3(HID / 64, 16, E), 256>>>(w1, w1316, D, HID,
        (long long)D * HID, (long long)2 * HID * D, 2, 0);
    transpose_f16_kernel<<<dim3(HID / 64, 16, E), 256>>>(w3, w1316, D, HID,
        (long long)D * HID, (long long)2 * HID * D, 2, 1);
    transpose_f16_kernel<<<dim3(16, HID / 64, E), 256>>>(w2, w216, HID, D,
        (long long)HID * D, (long long)D * HID, 1, 0);

    // 1) attn rmsnorm -> fp16
    rmsnorm_kernel<<<T, 256>>>(x, anw, nullptr, xn16);
    // 2) fused QKV projection + RoPE -> fp16 (q pre-scaled by 1/8)
    qkv_rope_kernel<<<dim3(12, 32), 256, GSMEM>>>(xn16, wq16, wk16, wv16,
                                                  q16, k16, v16, fcos, fsin);
    // 3) causal flash attention (fp16 MMA)
    attn_f16_kernel<<<dim3(S / 64, H, B), 128, ATTN_SMEM>>>(q16, k16, v16, at16);
    // 4) output projection + residual: h = x + at @ wo
    gemm_f16<<<dim3(8, 32, 1), 256, GSMEM>>>(at16, wo16, h, nullptr, x,
        nullptr, nullptr, T, D, H * HD, 1, 0, 0, 0);
    // 5) ffn rmsnorm -> fp32 (router!) + fp16 (experts)
    rmsnorm_kernel<<<T, 256>>>(h, fnw, hn, hn16);
    // 6) routing (fp32 — discrete decisions must not be perturbed)
    zero_cnt_kernel<<<1, 32>>>(cnt);
    router_kernel<<<T, 256>>>(hn, gw, cnt, tok, wt, slot);
    // 7) expert FFNs: fused w1/w3 glu GEMM, then w2 -> fp16 buf
    gemm_f16<<<dim3(2 * HID / 128, T / 128, E), 256, GSMEM>>>(hn16, w1316,
        nullptr, act16, nullptr, tok, cnt, T, 2 * HID, D, 5,
        0, (long long)2 * HID * D, (long long)T * HID);
    gemm_f16<<<dim3(8, 32, E), 256, GSMEM>>>(act16, w216, nullptr, buf16, nullptr,
        nullptr, cnt, T, D, HID, 0, (long long)T * HID, (long long)D * HID, (long long)T * D);
    // 8) out = h + w0*buf[slot0] + w1*buf[slot1]
    moe_combine_kernel<<<T, 256>>>(h, buf16, slot, wt, out);
}

// round 17
// speedup vs baseline: 1.1200x; 1.1200x over previous
#include <cuda_runtime.h>
#include <cuda_fp16.h>
#include <cstdint>

// Problem constants
constexpr int B = 4, S = 1024, D = 1024, H = 16, KH = 4, HD = 64;
constexpr int E = 8, HID = 2816;
constexpr int T = B * S;               // 4096 tokens
constexpr int NREP = H / KH;           // 4

// fp16 GEMM tile config: CTA 128x128, BK=32, 3 stages, 8 warps of 64x32, LDSM
constexpr int STG = 3;
constexpr int AH = 40;                 // halfs per smem row (32 used + 8 pad)
constexpr int ABUF = 128 * AH;
constexpr int BBUF = 128 * AH;
constexpr size_t GSMEM = (size_t)STG * (ABUF + BBUF) * sizeof(__half);  // 61440 B

// fp16 attention: rows padded to 72 halfs
constexpr int AP = 72;
constexpr size_t ATTN_SMEM = (size_t)5 * 64 * AP * sizeof(__half);      // 46080 B

// ---------------- scratch (device globals; no allocation allowed) -------------
__device__ __half g_xn16[(size_t)T * D];
__device__ __half g_q16[(size_t)T * H * HD];
__device__ __half g_k16[(size_t)T * KH * HD];
__device__ __half g_v16[(size_t)T * KH * HD];
__device__ __half g_at16[(size_t)T * H * HD];
__device__ float  g_h [(size_t)T * D];
__device__ float  g_hn[(size_t)T * D];        // fp32 for ROUTER (discrete decisions!)
__device__ __half g_hn16[(size_t)T * D];
__device__ __half g_act16[(size_t)E * T * HID];
__device__ __half g_buf16[(size_t)E * T * D];
__device__ int    g_cnt[E];
__device__ int    g_tok[E * T];
__device__ float  g_wt [E * T];
__device__ int    g_slot[2 * T];
// fp16 transposed weights [N][K]
__device__ __half g_wq16[(size_t)(H * HD) * D];
__device__ __half g_wk16[(size_t)(KH * HD) * D];
__device__ __half g_wv16[(size_t)(KH * HD) * D];
__device__ __half g_wo16[(size_t)D * (H * HD)];
__device__ __half g_w1316[(size_t)E * 2 * HID * D];   // interleaved: even=w1, odd=w3
__device__ __half g_w216[(size_t)E * D * HID];

// ---------------- mma / cp.async / ldmatrix helpers ----------------
__device__ __forceinline__ void mma_f16(float d[4], const uint32_t a[4], const uint32_t b[2]) {
    asm volatile(
        "mma.sync.aligned.m16n8k16.row.col.f32.f16.f16.f32 "
        "{%0,%1,%2,%3},{%4,%5,%6,%7},{%8,%9},{%0,%1,%2,%3};\n"
        : "+f"(d[0]), "+f"(d[1]), "+f"(d[2]), "+f"(d[3])
        : "r"(a[0]), "r"(a[1]), "r"(a[2]), "r"(a[3]), "r"(b[0]), "r"(b[1]));
}
__device__ __forceinline__ void ldsm_x4(uint32_t r[4], uint32_t addr) {
    asm volatile("ldmatrix.sync.aligned.m8n8.x4.shared.b16 {%0,%1,%2,%3}, [%4];"
        : "=r"(r[0]), "=r"(r[1]), "=r"(r[2]), "=r"(r[3]) : "r"(addr));
}
__device__ __forceinline__ void ldsm_x4_t(uint32_t r[4], uint32_t addr) {
    asm volatile("ldmatrix.sync.aligned.m8n8.x4.trans.shared.b16 {%0,%1,%2,%3}, [%4];"
        : "=r"(r[0]), "=r"(r[1]), "=r"(r[2]), "=r"(r[3]) : "r"(addr));
}
__device__ __forceinline__ void cp16(void* dst, const void* src, bool ok) {
    uint32_t d = (uint32_t)__cvta_generic_to_shared(dst);
    int sz = ok ? 16 : 0;
    asm volatile("cp.async.ca.shared.global [%0], [%1], 16, %2;\n"
                 :: "r"(d), "l"(src), "r"(sz));
}
__device__ __forceinline__ void cp_commit() { asm volatile("cp.async.commit_group;\n"); }
template<int N> __device__ __forceinline__ void cp_wait() {
    asm volatile("cp.async.wait_group %0;\n" :: "n"(N));
}

// ------- transpose+convert: [K][N] fp32 -> [N*rs + off][K] fp16, 64x64 tiles --
__global__ __launch_bounds__(256) void transpose_f16_kernel(
        const float* __restrict__ in, __half* __restrict__ out,
        int K, int N, long long inZ, long long outZ, int rs, int off) {
    __shared__ float tile[64][65];
    int z = blockIdx.z;
    const float* inz = in + (size_t)z * inZ;
    __half* outz = out + (size_t)z * outZ;
    int n0 = blockIdx.x * 64, k0 = blockIdx.y * 64;
    int tx = threadIdx.x & 15, ty = threadIdx.x >> 4;
    #pragma unroll
    for (int j = 0; j < 4; j++) {
        int kk = ty + j * 16;
        float4 v = *(const float4*)&inz[(size_t)(k0 + kk) * N + n0 + tx * 4];
        tile[kk][tx * 4 + 0] = v.x; tile[kk][tx * 4 + 1] = v.y;
        tile[kk][tx * 4 + 2] = v.z; tile[kk][tx * 4 + 3] = v.w;
    }
    __syncthreads();
    int sx = threadIdx.x & 7, sy = threadIdx.x >> 3;
    #pragma unroll
    for (int j = 0; j < 2; j++) {
        int nn = sy + j * 32;
        __half tmp[8];
        #pragma unroll
        for (int t = 0; t < 8; t++) tmp[t] = __float2half(tile[sx * 8 + t][nn]);
        *(uint4*)&outz[((size_t)(n0 + nn) * rs + off) * K + k0 + sx * 8] = *(uint4*)tmp;
    }
}

// ---------------- RMSNorm (fp32 and/or fp16 outputs) ----------------
__global__ __launch_bounds__(256) void rmsnorm_kernel(const float* __restrict__ x,
        const float* __restrict__ w, float* __restrict__ out, __half* __restrict__ out16) {
    int row = blockIdx.x;
    const float* xr = x + (size_t)row * D;
    float s = 0.f;
    for (int i = threadIdx.x; i < D; i += 256) { float v = xr[i]; s += v * v; }
    __shared__ float red[256];
    red[threadIdx.x] = s;
    __syncthreads();
    for (int o = 128; o > 0; o >>= 1) {
        if (threadIdx.x < o) red[threadIdx.x] += red[threadIdx.x + o];
        __syncthreads();
    }
    float inv = rsqrtf(red[0] / (float)D + 1e-5f);
    for (int i = threadIdx.x; i < D; i += 256) {
        float v = xr[i] * inv * w[i];
        if (out)   out[(size_t)row * D + i] = v;
        if (out16) out16[(size_t)row * D + i] = __float2half(v);
    }
}

// ============ fp16 GEMM: CTA 128x128, warp 64x32, BK=32, LDSM fragments =======
// A fp16 [m][K]; B fp16 [N][K]. modes: 0 plain, 1 +add(fp32)->fp32,
// 5 fused glu: out half at col/2 = silu(v_even)*v_odd (B rows interleaved w1/w3).
__global__ __launch_bounds__(256, 2) void gemm_f16(
        const __half* __restrict__ A, const __half* __restrict__ Bw,
        float* __restrict__ C, __half* __restrict__ C16,
        const float* __restrict__ add,
        const int* __restrict__ gtok, const int* __restrict__ gcnt,
        int M, int N, int K, int mode,
        long long strideAz, long long strideBz, long long strideCz) {
    int z = blockIdx.z;
    const __half* Az = A + (size_t)z * strideAz;
    const __half* Bz = Bw + (size_t)z * strideBz;
    float* Cz = C ? C + (size_t)z * strideCz : nullptr;
    __half* C16z = C16 ? C16 + (size_t)z * strideCz : nullptr;

    int c = gcnt ? gcnt[z] : M;
    int bm = blockIdx.y * 128;
    if (bm >= c) return;
    int bn = blockIdx.x * 128;

    extern __shared__ __half hsm[];
    __half* As = hsm;
    __half* Bs = hsm + STG * ABUF;
    uint32_t asm_base = (uint32_t)__cvta_generic_to_shared(As);
    uint32_t bsm_base = (uint32_t)__cvta_generic_to_shared(Bs);

    int tid = threadIdx.x;
    int ar = tid >> 1, ac = (tid & 1) * 16;
    const __half* aRow = nullptr;
    if (gtok) {
        if (bm + ar < c) aRow = Az + (size_t)(gtok + z * T)[bm + ar] * K;
    } else {
        if (bm + ar < c) aRow = Az + (size_t)(bm + ar) * K;
    }
    bool aok = aRow != nullptr;
    const __half* bPtr = Bz + (size_t)(bn + ar) * K + ac;

    int warp = tid >> 5, lane = tid & 31;
    int wm = (warp >> 2) * 64, wn = (warp & 3) * 32;
    int lr = lane >> 2, lc = lane & 3;
    int l7 = lane & 7, g = lane >> 3;

    int aoff[4], boff[2];
    #pragma unroll
    for (int mt = 0; mt < 4; mt++)
        aoff[mt] = (wm + mt * 16 + l7 + ((g & 1) << 3)) * AH + ((g >> 1) << 3);
    #pragma unroll
    for (int p = 0; p < 2; p++)
        boff[p] = (wn + (p << 4) + l7 + ((g >> 1) << 3)) * AH + ((g & 1) << 3);

    float acc[4][4][4] = {};

    auto stage = [&](int kb, int buf) {
        int ko = kb * 32;
        const __half* as = aok ? (aRow + ko + ac) : (const __half*)Bz;
        cp16(&As[buf * ABUF + ar * AH + ac],     as,              aok);
        cp16(&As[buf * ABUF + ar * AH + ac + 8], aok ? as + 8 : as, aok);
        cp16(&Bs[buf * BBUF + ar * AH + ac],     bPtr + ko,     true);
        cp16(&Bs[buf * BBUF + ar * AH + ac + 8], bPtr + ko + 8, true);
    };

    int nk = K >> 5;
    stage(0, 0); cp_commit();
    stage(1, 1); cp_commit();

    for (int kb = 0; kb < nk; kb++) {
        if (kb + 1 < nk) cp_wait<1>(); else cp_wait<0>();
        __syncthreads();
        int cur = kb % 3;
        uint32_t ab = asm_base + (uint32_t)(cur * ABUF) * 2;
        uint32_t bb = bsm_base + (uint32_t)(cur * BBUF) * 2;
        #pragma unroll
        for (int k8 = 0; k8 < 2; k8++) {
            int kk = k8 * 16;
            uint32_t af[4][4], bf[2][4];
            #pragma unroll
            for (int mt = 0; mt < 4; mt++) ldsm_x4(af[mt], ab + (uint32_t)(aoff[mt] + kk) * 2);
            #pragma unroll
            for (int p = 0; p < 2; p++)    ldsm_x4(bf[p],  bb + (uint32_t)(boff[p] + kk) * 2);
            #pragma unroll
            for (int mt = 0; mt < 4; mt++)
                #pragma unroll
                for (int nt = 0; nt < 4; nt++)
                    mma_f16(acc[mt][nt], af[mt], &bf[nt >> 1][(nt & 1) * 2]);
        }
        if (kb + 2 < nk) { stage(kb + 2, (kb + 2) % 3); cp_commit(); }
    }

    #pragma unroll
    for (int mt = 0; mt < 4; mt++) {
        #pragma unroll
        for (int nt = 0; nt < 4; nt++) {
            int col = bn + wn + nt * 8 + 2 * lc;
            #pragma unroll
            for (int half = 0; half < 2; half++) {
                int r = bm + wm + mt * 16 + lr + half * 8;
                if (r >= c) continue;
                float v0 = acc[mt][nt][half * 2 + 0];
                float v1 = acc[mt][nt][half * 2 + 1];
                if (mode == 5) {
                    float sv = v0 / (1.f + __expf(-v0)) * v1;
                    C16z[(size_t)r * (N >> 1) + (col >> 1)] = __float2half(sv);
                } else {
                    size_t idx = (size_t)r * N + col;
                    if (mode == 1) {
                        v0 += add[idx]; v1 += add[idx + 1];
                        *(float2*)&Cz[idx] = make_float2(v0, v1);
                    } else if (C16z) {
                        *(__half2*)&C16z[idx] = __floats2half2_rn(v0, v1);
                    } else {
                        *(float2*)&Cz[idx] = make_float2(v0, v1);
                    }
                }
            }
        }
    }
}

// ============ fused QKV projection + RoPE -> fp16 q/k/v (q pre-scaled) ========
__global__ __launch_bounds__(256, 2) void qkv_rope_kernel(
        const __half* __restrict__ xn,
        const __half* __restrict__ wq, const __half* __restrict__ wk,
        const __half* __restrict__ wv,
        __half* __restrict__ q, __half* __restrict__ k, __half* __restrict__ v,
        const float* __restrict__ fcos, const float* __restrict__ fsin) {
    int bm = blockIdx.y * 128;
    int bn = blockIdx.x * 128;
    const __half* Bsel; __half* Cout; int Nl, bnn; bool dorope; float osc;
    if (bn < 1024)      { Bsel = wq; Cout = q; Nl = 1024; bnn = bn;        dorope = true;  osc = 0.125f; }
    else if (bn < 1280) { Bsel = wk; Cout = k; Nl = 256;  bnn = bn - 1024; dorope = true;  osc = 1.f; }
    else                { Bsel = wv; Cout = v; Nl = 256;  bnn = bn - 1280; dorope = false; osc = 1.f; }

    extern __shared__ __half hsm[];
    __half* As = hsm;
    __half* Bs = hsm + STG * ABUF;
    uint32_t asm_base = (uint32_t)__cvta_generic_to_shared(As);
    uint32_t bsm_base = (uint32_t)__cvta_generic_to_shared(Bs);

    int tid = threadIdx.x;
    int ar = tid >> 1, ac = (tid & 1) * 16;
    const __half* aRow = xn + (size_t)(bm + ar) * D;
    const __half* bPtr = Bsel + (size_t)(bnn + ar) * D + ac;

    int warp = tid >> 5, lane = tid & 31;
    int wm = (warp >> 2) * 64, wn = (warp & 3) * 32;
    int lr = lane >> 2, lc = lane & 3;
    int l7 = lane & 7, g = lane >> 3;

    int aoff[4], boff[2];
    #pragma unroll
    for (int mt = 0; mt < 4; mt++)
        aoff[mt] = (wm + mt * 16 + l7 + ((g & 1) << 3)) * AH + ((g >> 1) << 3);
    #pragma unroll
    for (int p = 0; p < 2; p++)
        boff[p] = (wn + (p << 4) + l7 + ((g >> 1) << 3)) * AH + ((g & 1) << 3);

    float acc[4][4][4] = {};

    auto stage = [&](int kb, int buf) {
        int ko = kb * 32;
        const __half* as = aRow + ko + ac;
        cp16(&As[buf * ABUF + ar * AH + ac],     as,     true);
        cp16(&As[buf * ABUF + ar * AH + ac + 8], as + 8, true);
        cp16(&Bs[buf * BBUF + ar * AH + ac],     bPtr + ko,     true);
        cp16(&Bs[buf * BBUF + ar * AH + ac + 8], bPtr + ko + 8, true);
    };

    constexpr int nk = D / 32;
    stage(0, 0); cp_commit();
    stage(1, 1); cp_commit();

    for (int kb = 0; kb < nk; kb++) {
        if (kb + 1 < nk) cp_wait<1>(); else cp_wait<0>();
        __syncthreads();
        int cur = kb % 3;
        uint32_t ab = asm_base + (uint32_t)(cur * ABUF) * 2;
        uint32_t bb = bsm_base + (uint32_t)(cur * BBUF) * 2;
        #pragma unroll
        for (int k8 = 0; k8 < 2; k8++) {
            int kk = k8 * 16;
            uint32_t af[4][4], bf[2][4];
            #pragma unroll
            for (int mt = 0; mt < 4; mt++) ldsm_x4(af[mt], ab + (uint32_t)(aoff[mt] + kk) * 2);
            #pragma unroll
            for (int p = 0; p < 2; p++)    ldsm_x4(bf[p],  bb + (uint32_t)(boff[p] + kk) * 2);
            #pragma unroll
            for (int mt = 0; mt < 4; mt++)
                #pragma unroll
                for (int nt = 0; nt < 4; nt++)
                    mma_f16(acc[mt][nt], af[mt], &bf[nt >> 1][(nt & 1) * 2]);
        }
        if (kb + 2 < nk) { stage(kb + 2, (kb + 2) % 3); cp_commit(); }
    }

    #pragma unroll
    for (int mt = 0; mt < 4; mt++) {
        #pragma unroll
        for (int nt = 0; nt < 4; nt++) {
            int col = bnn + wn + nt * 8 + 2 * lc;
            int i = (col & 63) >> 1;
            #pragma unroll
            for (int half = 0; half < 2; half++) {
                int r = bm + wm + mt * 16 + lr + half * 8;
                float v0 = acc[mt][nt][half * 2 + 0];
                float v1 = acc[mt][nt][half * 2 + 1];
                if (dorope) {
                    int s = r & (S - 1);
                    float cs = fcos[s * 32 + i], sn = fsin[s * 32 + i];
                    float t0 = v0 * cs - v1 * sn;
                    v1 = v0 * sn + v1 * cs;
                    v0 = t0;
                }
                *(__half2*)&Cout[(size_t)r * Nl + col] = __floats2half2_rn(v0 * osc, v1 * osc);
            }
        }
    }
}

// ============ fp16 tensor-core flash attention (causal, GQA, m16n8k16) ========
__global__ __launch_bounds__(128) void attn_f16_kernel(const __half* __restrict__ q,
        const __half* __restrict__ k, const __half* __restrict__ v,
        __half* __restrict__ o16) {
    extern __shared__ __half hsm[];
    __half* Qs = hsm;
    __half* Ps = hsm;
    __half* Ks = hsm + 64 * AP;
    __half* Vs = Ks + 2 * 64 * AP;
    uint32_t pbase = (uint32_t)__cvta_generic_to_shared(Ps);
    uint32_t kbase = (uint32_t)__cvta_generic_to_shared(Ks);
    uint32_t vbase = (uint32_t)__cvta_generic_to_shared(Vs);

    const int qt = gridDim.x - 1 - blockIdx.x;
    const int h = blockIdx.y, b = blockIdx.z;
    const int kh = h / NREP;
    const int tid = threadIdx.x;
    const int warp = tid >> 5, lane = tid & 31;
    const int lr = lane >> 2, lc = lane & 3;
    const int wm = warp * 16;
    const int l7 = lane & 7, g = lane >> 3;

    const __half* krow = k + ((size_t)(b * S) * KH + kh) * HD;
    const __half* vrow = v + ((size_t)(b * S) * KH + kh) * HD;

    auto stageKV = [&](int kt, int buf) {
        __half* Kd = Ks + buf * 64 * AP;
        __half* Vd = Vs + buf * 64 * AP;
        #pragma unroll
        for (int j = 0; j < 4; j++) {
            int idx = tid + j * 128;
            int row = idx >> 3, ch = (idx & 7) * 8;
            size_t go = (size_t)(kt * 64 + row) * (KH * HD) + ch;
            cp16(&Kd[row * AP + ch], krow + go, true);
            cp16(&Vd[row * AP + ch], vrow + go, true);
        }
    };
    stageKV(0, 0);
    cp_commit();

    #pragma unroll
    for (int j = 0; j < 4; j++) {
        int idx = tid + j * 128;
        int row = idx >> 3, ch = (idx & 7) * 8;
        *(uint4*)&Qs[row * AP + ch] =
            *(const uint4*)&q[(size_t)(b * S + qt * 64 + row) * (H * HD) + h * HD + ch];
    }
    __syncthreads();
    uint32_t qf[4][4];
    #pragma unroll
    for (int ks = 0; ks < 4; ks++) {
        uint32_t addr = pbase + (uint32_t)((wm + l7 + ((g & 1) << 3)) * AP
                                           + ks * 16 + ((g >> 1) << 3)) * 2;
        ldsm_x4(qf[ks], addr);
    }

    float of[8][4] = {};
    float l0 = 0.f, l1 = 0.f;

    for (int kt = 0; kt <= qt; kt++) {
        int cur = kt & 1;
        if (kt < qt) { stageKV(kt + 1, cur ^ 1); cp_commit(); cp_wait<1>(); }
        else         { cp_wait<0>(); }
        __syncthreads();
        uint32_t kb = kbase + (uint32_t)(cur * 64 * AP) * 2;
        uint32_t vb = vbase + (uint32_t)(cur * 64 * AP) * 2;

        float sacc[8][4] = {};
        #pragma unroll
        for (int ks = 0; ks < 4; ks++) {
            #pragma unroll
            for (int np = 0; np < 4; np++) {
                uint32_t bf[4];
                uint32_t addr = kb + (uint32_t)((np * 16 + l7 + ((g >> 1) << 3)) * AP
                                                + ks * 16 + ((g & 1) << 3)) * 2;
                ldsm_x4(bf, addr);
                mma_f16(sacc[np * 2 + 0], qf[ks], &bf[0]);
                mma_f16(sacc[np * 2 + 1], qf[ks], &bf[2]);
            }
        }
        bool diag = (kt == qt);
        float ls0 = 0.f, ls1 = 0.f;
        #pragma unroll
        for (int nt = 0; nt < 8; nt++) {
            int c0 = nt * 8 + 2 * lc;
            int r0 = wm + lr, r1 = r0 + 8;
            float p00 = (diag && (c0     > r0)) ? 0.f : __expf(sacc[nt][0]);
            float p01 = (diag && (c0 + 1 > r0)) ? 0.f : __expf(sacc[nt][1]);
            float p10 = (diag && (c0     > r1)) ? 0.f : __expf(sacc[nt][2]);
            float p11 = (diag && (c0 + 1 > r1)) ? 0.f : __expf(sacc[nt][3]);
            ls0 += p00 + p01; ls1 += p10 + p11;
            *(__half2*)&Ps[r0 * AP + c0] = __floats2half2_rn(p00, p01);
            *(__half2*)&Ps[r1 * AP + c0] = __floats2half2_rn(p10, p11);
        }
        ls0 += __shfl_xor_sync(0xffffffffu, ls0, 1);
        ls0 += __shfl_xor_sync(0xffffffffu, ls0, 2);
        ls1 += __shfl_xor_sync(0xffffffffu, ls1, 1);
        ls1 += __shfl_xor_sync(0xffffffffu, ls1, 2);
        l0 += ls0; l1 += ls1;
        __syncwarp();

        #pragma unroll
        for (int ks = 0; ks < 4; ks++) {
            uint32_t paf[4];
            uint32_t addr = pbase + (uint32_t)((wm + l7 + ((g & 1) << 3)) * AP
                                               + ks * 16 + ((g >> 1) << 3)) * 2;
            ldsm_x4(paf, addr);
            #pragma unroll
            for (int np = 0; np < 4; np++) {
                uint32_t bf[4];
                uint32_t va = vb + (uint32_t)((ks * 16 + l7 + ((g & 1) << 3)) * AP
                                              + np * 16 + ((g >> 1) << 3)) * 2;
                ldsm_x4_t(bf, va);
                mma_f16(of[np * 2 + 0], paf, &bf[0]);
                mma_f16(of[np * 2 + 1], paf, &bf[2]);
            }
        }
        __syncthreads();
    }

    float i0 = 1.f / l0, i1 = 1.f / l1;
    size_t o0 = (size_t)(b * S + qt * 64 + wm + lr) * (H * HD) + h * HD;
    #pragma unroll
    for (int nt = 0; nt < 8; nt++) {
        int c0 = nt * 8 + 2 * lc;
        *(__half2*)&o16[o0 + c0] = __floats2half2_rn(of[nt][0] * i0, of[nt][1] * i0);
        *(__half2*)&o16[o0 + (size_t)8 * (H * HD) + c0] =
            __floats2half2_rn(of[nt][2] * i1, of[nt][3] * i1);
    }
}

// ---------------- router: top-2 of softmax(hn @ gate_w), fp32 (discrete!) -----
__global__ __launch_bounds__(256) void router_kernel(const float* __restrict__ hn,
        const float* __restrict__ gw, int* __restrict__ cnt,
        int* __restrict__ tok, float* __restrict__ wt, int* __restrict__ slot) {
    int t = blockIdx.x;
    int warp = threadIdx.x >> 5, lane = threadIdx.x & 31;
    const float* hr = hn + (size_t)t * D;
    float s = 0.f;
    for (int i = lane; i < D; i += 32) s += hr[i] * gw[i * E + warp];
    #pragma unroll
    for (int o = 16; o > 0; o >>= 1) s += __shfl_xor_sync(0xffffffffu, s, o);
    __shared__ float lg[E];
    if (lane == 0) lg[warp] = s;
    __syncthreads();
    if (threadIdx.x == 0) {
        int i0 = 0;
        for (int i = 1; i < E; i++) if (lg[i] > lg[i0]) i0 = i;
        int i1 = (i0 == 0) ? 1 : 0;
        for (int i = 0; i < E; i++) { if (i == i0) continue; if (lg[i] > lg[i1]) i1 = i; }
        float e1 = expf(lg[i1] - lg[i0]);
        float w0 = 1.f / (1.f + e1);
        float w1 = e1 * w0;
        int p0 = atomicAdd(&cnt[i0], 1);
        tok[i0 * T + p0] = t; wt[i0 * T + p0] = w0;
        int p1 = atomicAdd(&cnt[i1], 1);
        tok[i1 * T + p1] = t; wt[i1 * T + p1] = w1;
        slot[t * 2]     = i0 * T + p0;
        slot[t * 2 + 1] = i1 * T + p1;
    }
}

__global__ void zero_cnt_kernel(int* cnt) { if (threadIdx.x < E) cnt[threadIdx.x] = 0; }

// ---------------- final combine: out = h + w0*buf16[s0] + w1*buf16[s1] --------
__global__ __launch_bounds__(256) void moe_combine_kernel(const float* __restrict__ h,
        const __half* __restrict__ buf, const int* __restrict__ slot,
        const float* __restrict__ wt, float* __restrict__ out) {
    int t = blockIdx.x;
    int s0 = slot[t * 2], s1 = slot[t * 2 + 1];
    float w0 = wt[s0], w1 = wt[s1];
    const float4* h4 = (const float4*)(h + (size_t)t * D);
    const __half2* b0 = (const __half2*)(buf + (size_t)s0 * D);
    const __half2* b1 = (const __half2*)(buf + (size_t)s1 * D);
    float4* o4 = (float4*)(out + (size_t)t * D);
    int i = threadIdx.x;
    float4 hv = h4[i];
    float2 a0 = __half22float2(b0[2 * i]),     a1 = __half22float2(b0[2 * i + 1]);
    float2 c0 = __half22float2(b1[2 * i]),     c1 = __half22float2(b1[2 * i + 1]);
    o4[i] = make_float4(hv.x + w0 * a0.x + w1 * c0.x,
                        hv.y + w0 * a0.y + w1 * c0.y,
                        hv.z + w0 * a1.x + w1 * c1.x,
                        hv.w + w0 * a1.y + w1 * c1.y);
}

// ------------------------------- launch -------------------------------------
extern "C" void kernel_launch(void* const* d_in, const int* in_sizes, int n_in,
                              void* d_out, int out_size) {
    const float* x    = (const float*)d_in[0];
    const float* fcos = (const float*)d_in[3];
    const float* fsin = (const float*)d_in[4];
    const float* anw  = (const float*)d_in[5];
    const float* fnw  = (const float*)d_in[6];
    const float* wq   = (const float*)d_in[7];
    const float* wk   = (const float*)d_in[8];
    const float* wv   = (const float*)d_in[9];
    const float* wo   = (const float*)d_in[10];
    const float* gw   = (const float*)d_in[11];
    const float* w1   = (const float*)d_in[12];
    const float* w2   = (const float*)d_in[13];
    const float* w3   = (const float*)d_in[14];
    float* out = (float*)d_out;

    __half *xn16, *q16, *k16, *v16, *at16, *hn16, *act16, *buf16;
    __half *wq16, *wk16, *wv16, *wo16, *w1316, *w216;
    float *h, *hn, *wt;
    int *cnt, *tok, *slot;
    cudaGetSymbolAddress((void**)&xn16, g_xn16);
    cudaGetSymbolAddress((void**)&q16,  g_q16);
    cudaGetSymbolAddress((void**)&k16,  g_k16);
    cudaGetSymbolAddress((void**)&v16,  g_v16);
    cudaGetSymbolAddress((void**)&at16, g_at16);
    cudaGetSymbolAddress((void**)&h,    g_h);
    cudaGetSymbolAddress((void**)&hn,   g_hn);
    cudaGetSymbolAddress((void**)&hn16, g_hn16);
    cudaGetSymbolAddress((void**)&act16, g_act16);
    cudaGetSymbolAddress((void**)&buf16, g_buf16);
    cudaGetSymbolAddress((void**)&cnt,  g_cnt);
    cudaGetSymbolAddress((void**)&tok,  g_tok);
    cudaGetSymbolAddress((void**)&wt,   g_wt);
    cudaGetSymbolAddress((void**)&slot, g_slot);
    cudaGetSymbolAddress((void**)&wq16, g_wq16);
    cudaGetSymbolAddress((void**)&wk16, g_wk16);
    cudaGetSymbolAddress((void**)&wv16, g_wv16);
    cudaGetSymbolAddress((void**)&wo16, g_wo16);
    cudaGetSymbolAddress((void**)&w1316, g_w1316);
    cudaGetSymbolAddress((void**)&w216, g_w216);

    cudaFuncSetAttribute(attn_f16_kernel, cudaFuncAttributeMaxDynamicSharedMemorySize, (int)ATTN_SMEM);
    cudaFuncSetAttribute(gemm_f16, cudaFuncAttributeMaxDynamicSharedMemorySize, (int)GSMEM);
    cudaFuncSetAttribute(qkv_rope_kernel, cudaFuncAttributeMaxDynamicSharedMemorySize, (int)GSMEM);

    // one-time stream/event setup (no device memory; identical work every call)
    static cudaStream_t side = nullptr;
    static cudaEvent_t evFork = nullptr, evJoin = nullptr;
    if (!side) {
        cudaStreamCreateWithFlags(&side, cudaStreamNonBlocking);
        cudaEventCreateWithFlags(&evFork, cudaEventDisableTiming);
        cudaEventCreateWithFlags(&evJoin, cudaEventDisableTiming);
    }

    // fork: expert-weight transposes on side stream (consumed only at step 7)
    cudaEventRecord(evFork, 0);
    cudaStreamWaitEvent(side, evFork, 0);
    transpose_f16_kernel<<<dim3(HID / 64, 16, E), 256, 0, side>>>(w1, w1316, D, HID,
        (long long)D * HID, (long long)2 * HID * D, 2, 0);
    transpose_f16_kernel<<<dim3(HID / 64, 16, E), 256, 0, side>>>(w3, w1316, D, HID,
        (long long)D * HID, (long long)2 * HID * D, 2, 1);
    transpose_f16_kernel<<<dim3(16, HID / 64, E), 256, 0, side>>>(w2, w216, HID, D,
        (long long)HID * D, (long long)D * HID, 1, 0);
    cudaEventRecord(evJoin, side);

    // main stream: attention-path weight transposes + compute chain
    transpose_f16_kernel<<<dim3(16, 16, 1), 256>>>(wq, wq16, D, H * HD, 0, 0, 1, 0);
    transpose_f16_kernel<<<dim3(4,  16, 1), 256>>>(wk, wk16, D, KH * HD, 0, 0, 1, 0);
    transpose_f16_kernel<<<dim3(4,  16, 1), 256>>>(wv, wv16, D, KH * HD, 0, 0, 1, 0);
    transpose_f16_kernel<<<dim3(16, 16, 1), 256>>>(wo, wo16, H * HD, D, 0, 0, 1, 0);

    // 1) attn rmsnorm -> fp16
    rmsnorm_kernel<<<T, 256>>>(x, anw, nullptr, xn16);
    // 2) fused QKV projection + RoPE -> fp16 (q pre-scaled by 1/8)
    qkv_rope_kernel<<<dim3(12, 32), 256, GSMEM>>>(xn16, wq16, wk16, wv16,
                                                  q16, k16, v16, fcos, fsin);
    // 3) causal flash attention (fp16 MMA)
    attn_f16_kernel<<<dim3(S / 64, H, B), 128, ATTN_SMEM>>>(q16, k16, v16, at16);
    // 4) output projection + residual: h = x + at @ wo
    gemm_f16<<<dim3(8, 32, 1), 256, GSMEM>>>(at16, wo16, h, nullptr, x,
        nullptr, nullptr, T, D, H * HD, 1, 0, 0, 0);
    // 5) ffn rmsnorm -> fp32 (router!) + fp16 (experts)
    rmsnorm_kernel<<<T, 256>>>(h, fnw, hn, hn16);
    // 6) routing (fp32 — discrete decisions must not be perturbed)
    zero_cnt_kernel<<<1, 32>>>(cnt);
    router_kernel<<<T, 256>>>(hn, gw, cnt, tok, wt, slot);

    // join: expert weights ready before MoE GEMMs
    cudaStreamWaitEvent(0, evJoin, 0);

    // 7) expert FFNs: fused w1/w3 glu GEMM, then w2 -> fp16 buf
    gemm_f16<<<dim3(2 * HID / 128, T / 128, E), 256, GSMEM>>>(hn16, w1316,
        nullptr, act16, nullptr, tok, cnt, T, 2 * HID, D, 5,
        0, (long long)2 * HID * D, (long long)T * HID);
    gemm_f16<<<dim3(8, 32, E), 256, GSMEM>>>(act16, w216, nullptr, buf16, nullptr,
        nullptr, cnt, T, D, HID, 0, (long long)T * HID, (long long)D * HID, (long long)T * D);
    // 8) out = h + w0*buf[slot0] + w1*buf[slot1]
    moe_combine_kernel<<<T, 256>>>(h, buf16, slot, wt, out);
}